// round 9
// baseline (speedup 1.0000x reference)
#include <cuda_runtime.h>
#include <cuda_fp16.h>
#include <math.h>
#include <stdint.h>

#define BATCH 4096
#define DIM   512
#define NCLS  10

#define BM 128
#define NBLK (BATCH / BM)            // 32
#define NTRI (NBLK * (NBLK + 1) / 2) // 528 upper-triangular tiles

#define NCHUNK 8                     // K chunks of 64 halves
#define KCHUNK 64
#define NSTAGE 3

#define RSTRIDE 144                          // bytes per smem row (64 fp16 + 16B pad)
#define TILE_BYTES (128 * RSTRIDE)           // 18432
#define ABUF(b) ((b) * 2 * TILE_BYTES)
#define BBUF(b) ((b) * 2 * TILE_BYTES + TILE_BYTES)
#define SMEM_DYN (NSTAGE * 2 * TILE_BYTES)   // 110592 bytes

// Scratch (device globals -- no allocation allowed)
__device__ __half g_normh[BATCH * DIM];  // fp16 normalized features (4 MB)
__device__ int    g_cls[BATCH];
__device__ float  g_pos[BATCH];
__device__ float  g_all[BATCH];

// ---------------------------------------------------------------------------
__device__ __forceinline__ uint32_t smem_u32(const void* p) {
    uint32_t a;
    asm("{ .reg .u64 t; cvta.to.shared.u64 t, %1; cvt.u32.u64 %0, t; }"
        : "=r"(a) : "l"(p));
    return a;
}

#define LDSM_X4(d, addr) \
    asm volatile("ldmatrix.sync.aligned.m8n8.x4.shared.b16 {%0,%1,%2,%3}, [%4];" \
                 : "=r"((d)[0]), "=r"((d)[1]), "=r"((d)[2]), "=r"((d)[3]) \
                 : "r"(addr))

__device__ __forceinline__ void mma_f16(float* c, const uint32_t* a,
                                        uint32_t b0, uint32_t b1) {
    asm volatile(
        "mma.sync.aligned.m16n8k16.row.col.f32.f16.f16.f32 "
        "{%0,%1,%2,%3}, {%4,%5,%6,%7}, {%8,%9}, {%0,%1,%2,%3};"
        : "+f"(c[0]), "+f"(c[1]), "+f"(c[2]), "+f"(c[3])
        : "r"(a[0]), "r"(a[1]), "r"(a[2]), "r"(a[3]), "r"(b0), "r"(b1));
}

__device__ __forceinline__ float fast_exp2(float x) {
    float r;
    asm("ex2.approx.ftz.f32 %0, %1;" : "=f"(r) : "f"(x));
    return r;
}

__device__ __forceinline__ uint32_t pack_h2(float a, float b) {
    uint32_t r;
    asm("{ .reg .b16 l, h;\n\t"
        "cvt.rn.f16.f32 l, %1;\n\t"
        "cvt.rn.f16.f32 h, %2;\n\t"
        "mov.b32 %0, {l, h}; }" : "=r"(r) : "f"(a), "f"(b));
    return r;
}

// ---------------------------------------------------------------------------
// Kernel 1: L2-normalize -> fp16, class id, zero accumulators.
// One warp per row; 64-thread blocks for fine-grained SM balance.
// ---------------------------------------------------------------------------
__global__ void __launch_bounds__(64)
normalize_kernel(const float* __restrict__ feats,
                 const float* __restrict__ labels) {
    const int wid = threadIdx.x >> 5;
    const int lane = threadIdx.x & 31;
    const int row = blockIdx.x * 2 + wid;

    float4 v[4];
    float ss = 0.0f;
#pragma unroll
    for (int k = 0; k < 4; k++) {
        v[k] = ((const float4*)(feats + row * DIM))[k * 32 + lane];
        ss += v[k].x * v[k].x + v[k].y * v[k].y + v[k].z * v[k].z + v[k].w * v[k].w;
    }
#pragma unroll
    for (int o = 16; o > 0; o >>= 1) ss += __shfl_xor_sync(0xffffffffu, ss, o);
    float inv = 1.0f / sqrtf(ss);

#pragma unroll
    for (int k = 0; k < 4; k++) {
        uint2 u;
        u.x = pack_h2(v[k].x * inv, v[k].y * inv);
        u.y = pack_h2(v[k].z * inv, v[k].w * inv);
        ((uint2*)(g_normh + row * DIM))[k * 32 + lane] = u;
    }

    if (lane < NCLS) {
        if (labels[row * NCLS + lane] > 0.5f) g_cls[row] = lane;
    }
    if (lane == 0) { g_pos[row] = 0.0f; g_all[row] = 0.0f; }
}

// ---------------------------------------------------------------------------
// Kernel 2: fp16 m16n8k16 symmetric Gram tile, 3-stage cp.async pipeline,
// K chunks of 64 (half the barriers). 512 threads = 16 warps, 32x32 tiles.
// ---------------------------------------------------------------------------
__global__ void __launch_bounds__(512, 2)
contrastive_mma_kernel() {
    extern __shared__ char smem[];
    __shared__ int clsA_s[128];
    __shared__ int clsB_s[128];
    const uint32_t sb = smem_u32(smem);

    const int tid = threadIdx.x;
    const int lane = tid & 31;
    const int wid = tid >> 5;
    const int wr = wid >> 2;        // 0..3 warp row (32 rows each)
    const int wc = wid & 3;         // 0..3 warp col (32 cols each)
    const int g = lane >> 2;        // 0..7
    const int tig = lane & 3;       // 0..3

    // map linear block index -> upper-triangular (by, bx), bx >= by
    int rem = blockIdx.x;
    int by = 0;
    while (rem >= (NBLK - by)) { rem -= (NBLK - by); by++; }
    const int bx = by + rem;
    const bool isDiag = (bx == by);
    const int rowBase = by * BM;
    const int colBase = bx * BM;

    if (tid < 128) clsA_s[tid] = g_cls[rowBase + tid];
    else if (tid < 256) clsB_s[tid - 128] = g_cls[colBase + (tid - 128)];

    // per-lane ldmatrix offsets (bytes within tile)
    const int mA = lane >> 3;       // matrix index 0..3
    const int rA = lane & 7;
    const uint32_t aOff = (uint32_t)((wr * 32 + (mA & 1) * 8 + rA) * RSTRIDE
                                     + (mA >> 1) * 16);
    const uint32_t bOff = (uint32_t)((wc * 32 + (mA >> 1) * 8 + rA) * RSTRIDE
                                     + (mA & 1) * 16);

    float acc[2][4][4];
#pragma unroll
    for (int mi = 0; mi < 2; mi++)
#pragma unroll
        for (int ni = 0; ni < 4; ni++)
#pragma unroll
            for (int r = 0; r < 4; r++) acc[mi][ni][r] = 0.0f;

    auto load_chunk = [&](int c) {
        const int buf = c % NSTAGE;
        const int k0 = c * KCHUNK;
#pragma unroll
        for (int it = 0; it < 4; it++) {
            int flat = it * 512 + tid;      // 0..2047 16B segments
            int tile = flat >> 10;          // 0 = A, 1 = B
            if (tile == 1 && isDiag) continue;   // diag: B aliases A
            int r = (flat >> 3) & 127;
            int seg = flat & 7;
            const __half* src = g_normh
                + (size_t)((tile ? colBase : rowBase) + r) * DIM + k0 + seg * 8;
            uint32_t dst = sb + (tile ? BBUF(buf) : ABUF(buf))
                         + r * RSTRIDE + seg * 16;
            asm volatile("cp.async.cg.shared.global [%0], [%1], 16;"
                         :: "r"(dst), "l"(src) : "memory");
        }
        asm volatile("cp.async.commit_group;" ::: "memory");
    };

    auto compute_chunk = [&](int buf) {
        const uint32_t aBase = sb + ABUF(buf) + aOff;
        const uint32_t bBase = (isDiag ? sb + ABUF(buf) : sb + BBUF(buf)) + bOff;
#pragma unroll
        for (int ks = 0; ks < 4; ks++) {       // four k16 steps per 64-chunk
            uint32_t a[2][4], b[2][4];
#pragma unroll
            for (int mi = 0; mi < 2; mi++)
                LDSM_X4(a[mi], aBase + mi * (16 * RSTRIDE) + ks * 32);
#pragma unroll
            for (int p = 0; p < 2; p++)        // p covers cols wc*32 + p*16
                LDSM_X4(b[p], bBase + p * (16 * RSTRIDE) + ks * 32);
#pragma unroll
            for (int mi = 0; mi < 2; mi++)
#pragma unroll
                for (int ni = 0; ni < 4; ni++)
                    mma_f16(acc[mi][ni], a[mi],
                            b[ni >> 1][2 * (ni & 1)], b[ni >> 1][2 * (ni & 1) + 1]);
        }
    };

    // ---- 3-stage pipelined mainloop: one __syncthreads per chunk ----
    load_chunk(0);
    load_chunk(1);
    for (int c = 0; c < NCHUNK; c++) {
        if (c < NCHUNK - 1)
            asm volatile("cp.async.wait_group 1;" ::: "memory");
        else
            asm volatile("cp.async.wait_group 0;" ::: "memory");
        __syncthreads();
        if (c + 2 < NCHUNK) load_chunk(c + 2);
        compute_chunk(c % NSTAGE);
    }

    // ---- register-only epilogue (no clip: |sim|<=1 -> |sim/T|<=14.3 < 20) ----
    const float SCL = 1.44269504088896f / 0.07f;   // exp(x/T) = exp2(x*SCL)

    int rcls[2][2], ccls[4][2];
#pragma unroll
    for (int mi = 0; mi < 2; mi++)
#pragma unroll
        for (int h = 0; h < 2; h++)
            rcls[mi][h] = clsA_s[wr * 32 + mi * 16 + h * 8 + g];
#pragma unroll
    for (int ni = 0; ni < 4; ni++)
#pragma unroll
        for (int q = 0; q < 2; q++)
            ccls[ni][q] = clsB_s[wc * 32 + ni * 8 + tig * 2 + q];

    float rAll[2][2], rPos[2][2], cAll[4][2], cPos[4][2];
#pragma unroll
    for (int i = 0; i < 2; i++)
#pragma unroll
        for (int h = 0; h < 2; h++) {
            rAll[i][h] = 0.0f; rPos[i][h] = 0.0f;
        }
#pragma unroll
    for (int i = 0; i < 4; i++)
#pragma unroll
        for (int q = 0; q < 2; q++) {
            cAll[i][q] = 0.0f; cPos[i][q] = 0.0f;
        }

#pragma unroll
    for (int mi = 0; mi < 2; mi++)
#pragma unroll
        for (int ni = 0; ni < 4; ni++)
#pragma unroll
            for (int h = 0; h < 2; h++)
#pragma unroll
                for (int q = 0; q < 2; q++) {
                    float e = fast_exp2(acc[mi][ni][h * 2 + q] * SCL);
                    if (isDiag) {
                        int rl = wr * 32 + mi * 16 + h * 8 + g;
                        int cl = wc * 32 + ni * 8 + tig * 2 + q;
                        if (rl == cl) e = 0.0f;
                    }
                    rAll[mi][h] += e;
                    cAll[ni][q] += e;
                    if (rcls[mi][h] == ccls[ni][q]) {
                        rPos[mi][h] += e;
                        cPos[ni][q] += e;
                    }
                }

    // row sums: reduce over tig (lane bits 0,1); wc warps combine via atomics
#pragma unroll
    for (int mi = 0; mi < 2; mi++)
#pragma unroll
        for (int h = 0; h < 2; h++) {
#pragma unroll
            for (int o = 1; o < 4; o <<= 1) {
                rAll[mi][h] += __shfl_xor_sync(0xffffffffu, rAll[mi][h], o);
                rPos[mi][h] += __shfl_xor_sync(0xffffffffu, rPos[mi][h], o);
            }
        }
    if (tig == 0) {
#pragma unroll
        for (int mi = 0; mi < 2; mi++)
#pragma unroll
            for (int h = 0; h < 2; h++) {
                int gr = rowBase + wr * 32 + mi * 16 + h * 8 + g;
                atomicAdd(&g_all[gr], rAll[mi][h]);
                atomicAdd(&g_pos[gr], rPos[mi][h]);
            }
    }

    // symmetric column sums (off-diagonal only): reduce over g (lane bits 2..4)
    if (!isDiag) {
#pragma unroll
        for (int ni = 0; ni < 4; ni++)
#pragma unroll
            for (int q = 0; q < 2; q++) {
#pragma unroll
                for (int o = 4; o < 32; o <<= 1) {
                    cAll[ni][q] += __shfl_xor_sync(0xffffffffu, cAll[ni][q], o);
                    cPos[ni][q] += __shfl_xor_sync(0xffffffffu, cPos[ni][q], o);
                }
            }
        if (g == 0) {
#pragma unroll
            for (int ni = 0; ni < 4; ni++)
#pragma unroll
                for (int q = 0; q < 2; q++) {
                    int gc = colBase + wc * 32 + ni * 8 + tig * 2 + q;
                    atomicAdd(&g_all[gc], cAll[ni][q]);
                    atomicAdd(&g_pos[gc], cPos[ni][q]);
                }
        }
    }
}

// ---------------------------------------------------------------------------
// Kernel 3: per-row loss + validity + mean  (single block, 1024 threads)
// ---------------------------------------------------------------------------
__global__ void finalize_kernel(float* __restrict__ out) {
    __shared__ int cnt[NCLS];
    __shared__ float s_tot[32];
    __shared__ float s_cnt[32];
    int t = threadIdx.x;  // 1024

    if (t < NCLS) cnt[t] = 0;
    __syncthreads();
    for (int r = t; r < BATCH; r += 1024) atomicAdd(&cnt[g_cls[r]], 1);
    __syncthreads();

    float total = 0.0f, nval = 0.0f;
    for (int r = t; r < BATCH; r += 1024) {
        int c = g_cls[r];
        if (cnt[c] >= 2) {
            float pos = g_pos[r];
            float all = g_all[r];
            total += -logf(pos / (all + 1e-8f) + 1e-8f);
            nval += 1.0f;
        }
    }
#pragma unroll
    for (int o = 16; o > 0; o >>= 1) {
        total += __shfl_xor_sync(0xffffffffu, total, o);
        nval  += __shfl_xor_sync(0xffffffffu, nval, o);
    }
    if ((t & 31) == 0) { s_tot[t >> 5] = total; s_cnt[t >> 5] = nval; }
    __syncthreads();
    if (t == 0) {
        float tt = 0.0f, nn = 0.0f;
#pragma unroll
        for (int w = 0; w < 32; w++) { tt += s_tot[w]; nn += s_cnt[w]; }
        out[0] = (nn > 0.0f) ? tt / nn : 0.0f;
    }
}

// ---------------------------------------------------------------------------
extern "C" void kernel_launch(void* const* d_in, const int* in_sizes, int n_in,
                              void* d_out, int out_size) {
    const float* features = (const float*)d_in[0];  // [4096, 512] f32
    const float* labels   = (const float*)d_in[1];  // [4096, 10]  f32
    float* out = (float*)d_out;

    cudaFuncSetAttribute(contrastive_mma_kernel,
                         cudaFuncAttributeMaxDynamicSharedMemorySize, SMEM_DYN);

    normalize_kernel<<<BATCH / 2, 64>>>(features, labels);
    contrastive_mma_kernel<<<NTRI, 512, SMEM_DYN>>>();
    finalize_kernel<<<1, 1024>>>(out);
}

// round 10
// speedup vs baseline: 1.0971x; 1.0971x over previous
#include <cuda_runtime.h>
#include <cuda_fp16.h>
#include <math.h>
#include <stdint.h>

#define BATCH 4096
#define DIM   512
#define NCLS  10

#define BM 128
#define NBLK (BATCH / BM)            // 32
#define NTRI (NBLK * (NBLK + 1) / 2) // 528 upper-triangular tiles

#define NCHUNK 8                     // K chunks of 64 halves
#define KCHUNK 64
#define NSTAGE 3

#define RSTRIDE 144                          // bytes per smem row (64 fp16 + 16B pad)
#define TILE_BYTES (128 * RSTRIDE)           // 18432
#define ABUF(b) ((b) * 2 * TILE_BYTES)
#define BBUF(b) ((b) * 2 * TILE_BYTES + TILE_BYTES)
#define SMEM_DYN (NSTAGE * 2 * TILE_BYTES)   // 110592 bytes

// Scratch (device globals -- no allocation allowed)
__device__ __half g_normh[BATCH * DIM];  // fp16 normalized features (4 MB)
__device__ int    g_cls[BATCH];
__device__ float  g_pos[BATCH];
__device__ float  g_all[BATCH];

// ---------------------------------------------------------------------------
__device__ __forceinline__ uint32_t smem_u32(const void* p) {
    uint32_t a;
    asm("{ .reg .u64 t; cvta.to.shared.u64 t, %1; cvt.u32.u64 %0, t; }"
        : "=r"(a) : "l"(p));
    return a;
}

#define LDSM_X4(d, addr) \
    asm volatile("ldmatrix.sync.aligned.m8n8.x4.shared.b16 {%0,%1,%2,%3}, [%4];" \
                 : "=r"((d)[0]), "=r"((d)[1]), "=r"((d)[2]), "=r"((d)[3]) \
                 : "r"(addr))

// fp16 accumulate: c/d are 2x b32 (4 halves) -- double-rate tensor path
__device__ __forceinline__ void mma_f16h(uint32_t* c, const uint32_t* a,
                                         uint32_t b0, uint32_t b1) {
    asm volatile(
        "mma.sync.aligned.m16n8k16.row.col.f16.f16.f16.f16 "
        "{%0,%1}, {%2,%3,%4,%5}, {%6,%7}, {%0,%1};"
        : "+r"(c[0]), "+r"(c[1])
        : "r"(a[0]), "r"(a[1]), "r"(a[2]), "r"(a[3]), "r"(b0), "r"(b1));
}

__device__ __forceinline__ float fast_exp2(float x) {
    float r;
    asm("ex2.approx.ftz.f32 %0, %1;" : "=f"(r) : "f"(x));
    return r;
}

__device__ __forceinline__ uint32_t pack_h2(float a, float b) {
    uint32_t r;
    asm("{ .reg .b16 l, h;\n\t"
        "cvt.rn.f16.f32 l, %1;\n\t"
        "cvt.rn.f16.f32 h, %2;\n\t"
        "mov.b32 %0, {l, h}; }" : "=r"(r) : "f"(a), "f"(b));
    return r;
}

// ---------------------------------------------------------------------------
// Kernel 1: L2-normalize -> fp16, class id, zero accumulators. Warp per row.
// ---------------------------------------------------------------------------
__global__ void __launch_bounds__(256)
normalize_kernel(const float* __restrict__ feats,
                 const float* __restrict__ labels) {
    const int wid = threadIdx.x >> 5;
    const int lane = threadIdx.x & 31;
    const int row = blockIdx.x * 8 + wid;

    float4 v[4];
    float ss = 0.0f;
#pragma unroll
    for (int k = 0; k < 4; k++) {
        v[k] = ((const float4*)(feats + row * DIM))[k * 32 + lane];
        ss += v[k].x * v[k].x + v[k].y * v[k].y + v[k].z * v[k].z + v[k].w * v[k].w;
    }
#pragma unroll
    for (int o = 16; o > 0; o >>= 1) ss += __shfl_xor_sync(0xffffffffu, ss, o);
    float inv = 1.0f / sqrtf(ss);

#pragma unroll
    for (int k = 0; k < 4; k++) {
        uint2 u;
        u.x = pack_h2(v[k].x * inv, v[k].y * inv);
        u.y = pack_h2(v[k].z * inv, v[k].w * inv);
        ((uint2*)(g_normh + row * DIM))[k * 32 + lane] = u;
    }

    if (lane < NCLS) {
        if (labels[row * NCLS + lane] > 0.5f) g_cls[row] = lane;
    }
    if (lane == 0) { g_pos[row] = 0.0f; g_all[row] = 0.0f; }
}

// ---------------------------------------------------------------------------
// Kernel 2: fp16-accumulate m16n8k16 symmetric Gram tile, 3-stage cp.async
// pipeline, K chunks of 64. 512 threads = 16 warps (4x4), 32x32 warp tiles.
// ---------------------------------------------------------------------------
__global__ void __launch_bounds__(512, 2)
contrastive_mma_kernel() {
    extern __shared__ char smem[];
    __shared__ int clsA_s[128];
    __shared__ int clsB_s[128];
    const uint32_t sb = smem_u32(smem);

    const int tid = threadIdx.x;
    const int lane = tid & 31;
    const int wid = tid >> 5;
    const int wr = wid >> 2;        // 0..3 warp row (32 rows each)
    const int wc = wid & 3;         // 0..3 warp col (32 cols each)
    const int g = lane >> 2;        // 0..7
    const int tig = lane & 3;       // 0..3

    // map linear block index -> upper-triangular (by, bx), bx >= by
    int rem = blockIdx.x;
    int by = 0;
    while (rem >= (NBLK - by)) { rem -= (NBLK - by); by++; }
    const int bx = by + rem;
    const bool isDiag = (bx == by);
    const int rowBase = by * BM;
    const int colBase = bx * BM;

    if (tid < 128) clsA_s[tid] = g_cls[rowBase + tid];
    else if (tid < 256) clsB_s[tid - 128] = g_cls[colBase + (tid - 128)];

    // per-lane ldmatrix offsets (bytes within tile)
    const int mA = lane >> 3;       // matrix index 0..3
    const int rA = lane & 7;
    const uint32_t aOff = (uint32_t)((wr * 32 + (mA & 1) * 8 + rA) * RSTRIDE
                                     + (mA >> 1) * 16);
    const uint32_t bOff = (uint32_t)((wc * 32 + (mA >> 1) * 8 + rA) * RSTRIDE
                                     + (mA & 1) * 16);

    // fp16 accumulators: [mi][ni][h] -> b32 holding cols (tig*2, tig*2+1)
    uint32_t hacc[2][4][2];
#pragma unroll
    for (int mi = 0; mi < 2; mi++)
#pragma unroll
        for (int ni = 0; ni < 4; ni++) {
            hacc[mi][ni][0] = 0u;
            hacc[mi][ni][1] = 0u;
        }

    auto load_chunk = [&](int c) {
        const int buf = c % NSTAGE;
        const int k0 = c * KCHUNK;
#pragma unroll
        for (int it = 0; it < 4; it++) {
            int flat = it * 512 + tid;      // 0..2047 16B segments
            int tile = flat >> 10;          // 0 = A, 1 = B
            if (tile == 1 && isDiag) continue;   // diag: B aliases A
            int r = (flat >> 3) & 127;
            int seg = flat & 7;
            const __half* src = g_normh
                + (size_t)((tile ? colBase : rowBase) + r) * DIM + k0 + seg * 8;
            uint32_t dst = sb + (tile ? BBUF(buf) : ABUF(buf))
                         + r * RSTRIDE + seg * 16;
            asm volatile("cp.async.cg.shared.global [%0], [%1], 16;"
                         :: "r"(dst), "l"(src) : "memory");
        }
        asm volatile("cp.async.commit_group;" ::: "memory");
    };

    auto compute_chunk = [&](int buf) {
        const uint32_t aBase = sb + ABUF(buf) + aOff;
        const uint32_t bBase = (isDiag ? sb + ABUF(buf) : sb + BBUF(buf)) + bOff;
#pragma unroll
        for (int ks = 0; ks < 4; ks++) {       // four k16 steps per 64-chunk
            uint32_t a[2][4], b[2][4];
#pragma unroll
            for (int mi = 0; mi < 2; mi++)
                LDSM_X4(a[mi], aBase + mi * (16 * RSTRIDE) + ks * 32);
#pragma unroll
            for (int p = 0; p < 2; p++)        // p covers cols wc*32 + p*16
                LDSM_X4(b[p], bBase + p * (16 * RSTRIDE) + ks * 32);
#pragma unroll
            for (int mi = 0; mi < 2; mi++)
#pragma unroll
                for (int ni = 0; ni < 4; ni++)
                    mma_f16h(hacc[mi][ni], a[mi],
                             b[ni >> 1][2 * (ni & 1)], b[ni >> 1][2 * (ni & 1) + 1]);
        }
    };

    // ---- 3-stage pipelined mainloop: one __syncthreads per chunk ----
    load_chunk(0);
    load_chunk(1);
    for (int c = 0; c < NCHUNK; c++) {
        if (c < NCHUNK - 1)
            asm volatile("cp.async.wait_group 1;" ::: "memory");
        else
            asm volatile("cp.async.wait_group 0;" ::: "memory");
        __syncthreads();
        if (c + 2 < NCHUNK) load_chunk(c + 2);
        compute_chunk(c % NSTAGE);
    }

    // ---- register-only epilogue (no clip: |sim|<=1 -> |sim/T|<=14.3 < 20) ----
    const float SCL = 1.44269504088896f / 0.07f;   // exp(x/T) = exp2(x*SCL)

    int rcls[2][2], ccls[4][2];
#pragma unroll
    for (int mi = 0; mi < 2; mi++)
#pragma unroll
        for (int h = 0; h < 2; h++)
            rcls[mi][h] = clsA_s[wr * 32 + mi * 16 + h * 8 + g];
#pragma unroll
    for (int ni = 0; ni < 4; ni++)
#pragma unroll
        for (int q = 0; q < 2; q++)
            ccls[ni][q] = clsB_s[wc * 32 + ni * 8 + tig * 2 + q];

    float rAll[2][2], rPos[2][2], cAll[4][2], cPos[4][2];
#pragma unroll
    for (int i = 0; i < 2; i++)
#pragma unroll
        for (int h = 0; h < 2; h++) {
            rAll[i][h] = 0.0f; rPos[i][h] = 0.0f;
        }
#pragma unroll
    for (int i = 0; i < 4; i++)
#pragma unroll
        for (int q = 0; q < 2; q++) {
            cAll[i][q] = 0.0f; cPos[i][q] = 0.0f;
        }

#pragma unroll
    for (int mi = 0; mi < 2; mi++)
#pragma unroll
        for (int ni = 0; ni < 4; ni++)
#pragma unroll
            for (int h = 0; h < 2; h++) {
                float2 vv = __half22float2(
                    *reinterpret_cast<__half2*>(&hacc[mi][ni][h]));
#pragma unroll
                for (int q = 0; q < 2; q++) {
                    float e = fast_exp2((q ? vv.y : vv.x) * SCL);
                    if (isDiag) {
                        int rl = wr * 32 + mi * 16 + h * 8 + g;
                        int cl = wc * 32 + ni * 8 + tig * 2 + q;
                        if (rl == cl) e = 0.0f;
                    }
                    rAll[mi][h] += e;
                    cAll[ni][q] += e;
                    if (rcls[mi][h] == ccls[ni][q]) {
                        rPos[mi][h] += e;
                        cPos[ni][q] += e;
                    }
                }
            }

    // row sums: reduce over tig (lane bits 0,1); wc warps combine via atomics
#pragma unroll
    for (int mi = 0; mi < 2; mi++)
#pragma unroll
        for (int h = 0; h < 2; h++) {
#pragma unroll
            for (int o = 1; o < 4; o <<= 1) {
                rAll[mi][h] += __shfl_xor_sync(0xffffffffu, rAll[mi][h], o);
                rPos[mi][h] += __shfl_xor_sync(0xffffffffu, rPos[mi][h], o);
            }
        }
    if (tig == 0) {
#pragma unroll
        for (int mi = 0; mi < 2; mi++)
#pragma unroll
            for (int h = 0; h < 2; h++) {
                int gr = rowBase + wr * 32 + mi * 16 + h * 8 + g;
                atomicAdd(&g_all[gr], rAll[mi][h]);
                atomicAdd(&g_pos[gr], rPos[mi][h]);
            }
    }

    // symmetric column sums (off-diagonal only): reduce over g (lane bits 2..4)
    if (!isDiag) {
#pragma unroll
        for (int ni = 0; ni < 4; ni++)
#pragma unroll
            for (int q = 0; q < 2; q++) {
#pragma unroll
                for (int o = 4; o < 32; o <<= 1) {
                    cAll[ni][q] += __shfl_xor_sync(0xffffffffu, cAll[ni][q], o);
                    cPos[ni][q] += __shfl_xor_sync(0xffffffffu, cPos[ni][q], o);
                }
            }
        if (g == 0) {
#pragma unroll
            for (int ni = 0; ni < 4; ni++)
#pragma unroll
                for (int q = 0; q < 2; q++) {
                    int gc = colBase + wc * 32 + ni * 8 + tig * 2 + q;
                    atomicAdd(&g_all[gc], cAll[ni][q]);
                    atomicAdd(&g_pos[gc], cPos[ni][q]);
                }
        }
    }
}

// ---------------------------------------------------------------------------
// Kernel 3: per-row loss + validity + mean  (single block, 1024 threads)
// ---------------------------------------------------------------------------
__global__ void finalize_kernel(float* __restrict__ out) {
    __shared__ int cnt[NCLS];
    __shared__ float s_tot[32];
    __shared__ float s_cnt[32];
    int t = threadIdx.x;  // 1024

    if (t < NCLS) cnt[t] = 0;
    __syncthreads();
    for (int r = t; r < BATCH; r += 1024) atomicAdd(&cnt[g_cls[r]], 1);
    __syncthreads();

    float total = 0.0f, nval = 0.0f;
    for (int r = t; r < BATCH; r += 1024) {
        int c = g_cls[r];
        if (cnt[c] >= 2) {
            float pos = g_pos[r];
            float all = g_all[r];
            total += -logf(pos / (all + 1e-8f) + 1e-8f);
            nval += 1.0f;
        }
    }
#pragma unroll
    for (int o = 16; o > 0; o >>= 1) {
        total += __shfl_xor_sync(0xffffffffu, total, o);
        nval  += __shfl_xor_sync(0xffffffffu, nval, o);
    }
    if ((t & 31) == 0) { s_tot[t >> 5] = total; s_cnt[t >> 5] = nval; }
    __syncthreads();
    if (t == 0) {
        float tt = 0.0f, nn = 0.0f;
#pragma unroll
        for (int w = 0; w < 32; w++) { tt += s_tot[w]; nn += s_cnt[w]; }
        out[0] = (nn > 0.0f) ? tt / nn : 0.0f;
    }
}

// ---------------------------------------------------------------------------
extern "C" void kernel_launch(void* const* d_in, const int* in_sizes, int n_in,
                              void* d_out, int out_size) {
    const float* features = (const float*)d_in[0];  // [4096, 512] f32
    const float* labels   = (const float*)d_in[1];  // [4096, 10]  f32
    float* out = (float*)d_out;

    cudaFuncSetAttribute(contrastive_mma_kernel,
                         cudaFuncAttributeMaxDynamicSharedMemorySize, SMEM_DYN);

    normalize_kernel<<<BATCH / 8, 256>>>(features, labels);
    contrastive_mma_kernel<<<NTRI, 512, SMEM_DYN>>>();
    finalize_kernel<<<1, 1024>>>(out);
}